// round 11
// baseline (speedup 1.0000x reference)
#include <cuda_runtime.h>
#include <math.h>

#define NN 100000
#define EE 3200000
#define DIN 128
#define HH 256
#define MM 500
#define OO 100

// ---------------- scratch: __device__ globals (sanctioned; no dynamic alloc) ----
__device__ __align__(16) float g_dinv[NN];            // deg accumulator -> deg^-1/2
__device__ __align__(16) float g_z1[(size_t)NN*DIN];  // Sx + self*x
__device__ __align__(16) float g_h [(size_t)NN*HH];   // relu(z1 @ W1 + b1)
__device__ __align__(16) float g_z2[(size_t)NN*HH];   // Sh + self*h
__device__ __align__(16) int   g_src[EE];
__device__ __align__(16) int   g_dst[EE];
__device__ int g_is64;                                // edge dtype flag (recomputed per call)

// ---------------- edge dtype detection + normalization ----------------
// int64 data: first 16 words are valid node ids in [0, NN).
// int32 data read as int64: word = lo + (hi<<32); hi==0 with p=1e-5 -> 16 words all
// "valid" with p ~ 1e-80. Deterministic given the input.
__global__ void detect_dtype_kernel(const void* __restrict__ ei_raw) {
    if (threadIdx.x == 0 && blockIdx.x == 0) {
        const long long* e64 = (const long long*)ei_raw;
        int ok = 1;
        for (int k = 0; k < 16; k++) {
            long long v = e64[k];
            if (v < 0 || v >= NN) ok = 0;
        }
        g_is64 = ok;
    }
}

__global__ void convert_edges_kernel(const void* __restrict__ ei_raw) {
    int e = blockIdx.x * blockDim.x + threadIdx.x;
    if (e >= EE) return;
    if (g_is64) {
        const long long* e64 = (const long long*)ei_raw;
        g_src[e] = (int)e64[e];
        g_dst[e] = (int)e64[(size_t)EE + e];
    } else {
        const int* e32 = (const int*)ei_raw;
        g_src[e] = e32[e];
        g_dst[e] = e32[EE + e];
    }
}

// ---------------- degree / dinv ----------------
__global__ void zero_deg_kernel() {
    int i = blockIdx.x * blockDim.x + threadIdx.x;
    if (i < NN) g_dinv[i] = 0.0f;
}

__global__ void count_deg_kernel() {
    int e = blockIdx.x * blockDim.x + threadIdx.x;
    if (e < EE) atomicAdd(&g_dinv[g_dst[e]], 1.0f);
}

__global__ void finalize_dinv_kernel() {
    int i = blockIdx.x * blockDim.x + threadIdx.x;
    if (i < NN) g_dinv[i] = rsqrtf(g_dinv[i] + 2.0f);
}

// ---------------- self-loop init: acc = 2*dinv^2 * feat ----------------
template<int PHASE>
__global__ void selfinit_kernel(const float* __restrict__ xin) {
    constexpr int C = (PHASE == 0) ? DIN : HH;
    const float* feat = (PHASE == 0) ? xin : (const float*)g_h;
    float*       acc  = (PHASE == 0) ? g_z1 : g_z2;
    const int per_row = C / 4;
    int idx = blockIdx.x * blockDim.x + threadIdx.x;   // over N*C/4 float4s
    if (idx >= NN * per_row) return;
    int n = idx / per_row;
    float di = g_dinv[n];
    float sc = 2.0f * di * di;
    float4 v = reinterpret_cast<const float4*>(feat)[idx];
    v.x *= sc; v.y *= sc; v.z *= sc; v.w *= sc;
    reinterpret_cast<float4*>(acc)[idx] = v;
}

// ---------------- edge propagation: acc[dst] += coef * feat[src] ----------------
// one warp per edge; lane covers 4 floats per 128-channel chunk
template<int PHASE>
__global__ void prop_kernel(const float* __restrict__ xin) {
    constexpr int C = (PHASE == 0) ? DIN : HH;
    const float* feat = (PHASE == 0) ? xin : (const float*)g_h;
    float*       acc  = (PHASE == 0) ? g_z1 : g_z2;

    int warp = (blockIdx.x * blockDim.x + threadIdx.x) >> 5;
    int lane = threadIdx.x & 31;
    if (warp >= EE) return;
    int s = g_src[warp];
    int d = g_dst[warp];
    float coef = g_dinv[s] * g_dinv[d];
    const float4* fs = reinterpret_cast<const float4*>(feat + (size_t)s * C);
    float* ad = acc + (size_t)d * C;
#pragma unroll
    for (int r = 0; r < C / 128; r++) {
        float4 v = fs[lane + r * 32];
        int base = (lane + r * 32) * 4;
        atomicAdd(ad + base + 0, v.x * coef);
        atomicAdd(ad + base + 1, v.y * coef);
        atomicAdd(ad + base + 2, v.z * coef);
        atomicAdd(ad + base + 3, v.w * coef);
    }
}

// ---------------- fused SGEMM: C = epi(A' @ B + bias) ----------------
// MODE 0: relu epilogue        (GEMM1)  ASRC=1 (g_z1)  DST=1 (g_h)
// MODE 1: softplus epilogue    (GEMM2)  ASRC=2 (g_z2)  DST=0 (param)
// MODE 2: A' = tanh(sp(thr)*A) (GEMM3)  ASRC=0 (param) DST=0 (param)
#define BM 64
#define BN 64
#define BK 16
#define TM 4
#define TN 4

template<int MODE, int ASRC, int DSTSEL>
__global__ __launch_bounds__(256)
void sgemm_kernel(const float* __restrict__ Aparam, const float* __restrict__ B,
                  const float* __restrict__ bias, float* __restrict__ Cparam,
                  int Mrows, int K, int Ncols, const float* __restrict__ thr) {
    const float* A = (ASRC == 1) ? (const float*)g_z1
                   : (ASRC == 2) ? (const float*)g_z2
                                 : Aparam;
    float* Cp = (DSTSEL == 1) ? (float*)g_h : Cparam;

    __shared__ float As[BK][BM + 4];
    __shared__ float Bs[BK][BN + 4];

    float sp_t = 1.0f;
    if (MODE == 2) {
        float t = *thr;
        sp_t = fmaxf(t, 0.0f) + log1pf(expf(-fabsf(t)));
    }

    int tid = threadIdx.x;
    int tx = tid & 15;      // column group (0..15)
    int ty = tid >> 4;      // row group    (0..15)
    int rowBase = blockIdx.y * BM;
    int colBase = blockIdx.x * BN;

    float acc[TM][TN] = {};

    for (int k0 = 0; k0 < K; k0 += BK) {
        // load A tile (BM x BK)
        for (int i = tid; i < BM * BK; i += 256) {
            int r  = i / BK;
            int kk = i % BK;
            int gr = rowBase + r;
            int gk = k0 + kk;
            float v = 0.0f;
            if (gr < Mrows && gk < K) v = A[(size_t)gr * K + gk];
            if (MODE == 2) v = tanhf(sp_t * v);
            As[kk][r] = v;
        }
        // load B tile (BK x BN)
        for (int i = tid; i < BK * BN; i += 256) {
            int kk = i / BN;
            int c  = i % BN;
            int gk = k0 + kk;
            int gc = colBase + c;
            float v = 0.0f;
            if (gk < K && gc < Ncols) v = B[(size_t)gk * Ncols + gc];
            Bs[kk][c] = v;
        }
        __syncthreads();
#pragma unroll
        for (int kk = 0; kk < BK; kk++) {
            float av[TM], bv[TN];
#pragma unroll
            for (int i = 0; i < TM; i++) av[i] = As[kk][ty * TM + i];
#pragma unroll
            for (int j = 0; j < TN; j++) bv[j] = Bs[kk][tx * TN + j];
#pragma unroll
            for (int i = 0; i < TM; i++)
#pragma unroll
                for (int j = 0; j < TN; j++)
                    acc[i][j] = fmaf(av[i], bv[j], acc[i][j]);
        }
        __syncthreads();
    }

#pragma unroll
    for (int i = 0; i < TM; i++) {
        int gr = rowBase + ty * TM + i;
        if (gr >= Mrows) continue;
#pragma unroll
        for (int j = 0; j < TN; j++) {
            int gc = colBase + tx * TN + j;
            if (gc >= Ncols) continue;
            float v = acc[i][j] + bias[gc];
            if (MODE == 0) v = fmaxf(v, 0.0f);
            else if (MODE == 1) v = fmaxf(v, 0.0f) + log1pf(expf(-fabsf(v)));
            Cp[(size_t)gr * Ncols + gc] = v;
        }
    }
}

// ---------------- launch: ONLY kernel launches, no other CUDA API ----------------
extern "C" void kernel_launch(void* const* d_in, const int* in_sizes, int n_in,
                              void* d_out, int out_size) {
    const float* x    = (const float*)d_in[0];
    const void*  ei   = d_in[1];                 // int32 or int64 — detected on device
    const float* W1   = (const float*)d_in[2];
    const float* b1   = (const float*)d_in[3];
    const float* W2   = (const float*)d_in[4];
    const float* b2   = (const float*)d_in[5];
    const float* Wout = (const float*)d_in[6];
    const float* bout = (const float*)d_in[7];
    const float* thr  = (const float*)d_in[8];

    float* mr = (float*)d_out;                       // [N, M]
    float* y  = (float*)d_out + (size_t)NN * MM;     // [N, O]

    const int T = 256;

    // edge dtype detection + normalization to int32
    detect_dtype_kernel<<<1, 32>>>(ei);
    convert_edges_kernel<<<(EE + T - 1) / T, T>>>(ei);

    // degrees -> dinv
    zero_deg_kernel<<<(NN + T - 1) / T, T>>>();
    count_deg_kernel<<<(EE + T - 1) / T, T>>>();
    finalize_dinv_kernel<<<(NN + T - 1) / T, T>>>();

    // z1 = self*x ; z1 += S x
    selfinit_kernel<0><<<(NN * (DIN / 4) + T - 1) / T, T>>>(x);
    prop_kernel<0><<<EE / 8, T>>>(x);

    // h = relu(z1 @ W1 + b1)
    {
        dim3 grid((HH + BN - 1) / BN, (NN + BM - 1) / BM);
        sgemm_kernel<0, 1, 1><<<grid, 256>>>(nullptr, W1, b1, nullptr, NN, DIN, HH, nullptr);
    }

    // z2 = self*h ; z2 += S h
    selfinit_kernel<1><<<(NN * (HH / 4) + T - 1) / T, T>>>(nullptr);
    prop_kernel<1><<<EE / 8, T>>>(nullptr);

    // mr = softplus(z2 @ W2 + b2)
    {
        dim3 grid((MM + BN - 1) / BN, (NN + BM - 1) / BM);
        sgemm_kernel<1, 2, 0><<<grid, 256>>>(nullptr, W2, b2, mr, NN, HH, MM, nullptr);
    }

    // y = tanh(softplus(thr) * mr) @ Wout + bout
    {
        dim3 grid((OO + BN - 1) / BN, (NN + BM - 1) / BM);
        sgemm_kernel<2, 0, 0><<<grid, 256>>>(mr, Wout, bout, y, NN, MM, OO, thr);
    }
}

// round 15
// speedup vs baseline: 2.2213x; 2.2213x over previous
#include <cuda_runtime.h>
#include <math.h>

#define NN 100000
#define EE 3200000
#define DIN 128
#define HH 256
#define MM 500
#define OO 100

// ---------------- scratch: __device__ globals (sanctioned; no dynamic alloc) ----
__device__ __align__(16) float g_dinv[NN];            // deg^-1/2
__device__ __align__(16) int   g_degi[NN];            // int degree
__device__ __align__(16) int   g_cursor[NN];          // scatter cursors
__device__ __align__(16) int   g_rowptr[NN + 1];      // CSR row pointers (by dst)
__device__ __align__(16) int   g_csr[EE];             // CSR src indices
__device__ __align__(16) float g_z1[(size_t)NN*DIN];  // Sx + self*x
__device__ __align__(16) float g_h [(size_t)NN*HH];   // relu(z1 @ W1 + b1)
__device__ __align__(16) float g_z2[(size_t)NN*HH];   // Sh + self*h
__device__ int g_is64;                                // edge dtype flag

// ---------------- edge dtype detection ----------------
// int64 data: first 16 words are valid node ids in [0, NN).
// int32 data read as int64: hi word nonzero with p ~ 1-1e-5 per word.
__global__ __launch_bounds__(32)
void detect_dtype_kernel(const void* __restrict__ ei_raw) {
    if (threadIdx.x == 0 && blockIdx.x == 0) {
        const long long* e64 = (const long long*)ei_raw;
        int ok = 1;
        for (int k = 0; k < 16; k++) {
            long long v = e64[k];
            if (v < 0 || v >= NN) ok = 0;
        }
        g_is64 = ok;
    }
}

__device__ __forceinline__ void load_edge(const void* ei_raw, int e, int& s, int& d) {
    if (g_is64) {
        const long long* e64 = (const long long*)ei_raw;
        s = (int)e64[e];
        d = (int)e64[(size_t)EE + e];
    } else {
        const int* e32 = (const int*)ei_raw;
        s = e32[e];
        d = e32[EE + e];
    }
}

// ---------------- degree count ----------------
__global__ __launch_bounds__(256)
void zero_counts_kernel() {
    int i = blockIdx.x * blockDim.x + threadIdx.x;
    if (i < NN) { g_degi[i] = 0; g_cursor[i] = 0; }
}

__global__ __launch_bounds__(256)
void count_deg_kernel(const void* __restrict__ ei_raw) {
    int e = blockIdx.x * blockDim.x + threadIdx.x;
    if (e >= EE) return;
    int s, d; load_edge(ei_raw, e, s, d);
    atomicAdd(&g_degi[d], 1);
}

__global__ __launch_bounds__(256)
void finalize_dinv_kernel() {
    int i = blockIdx.x * blockDim.x + threadIdx.x;
    if (i < NN) g_dinv[i] = rsqrtf((float)g_degi[i] + 2.0f);
}

// ---------------- exclusive scan of degrees -> rowptr (single block) ----------------
// __launch_bounds__(1024) is REQUIRED: unbounded, ptxas allocates >64 regs/thread
// and 1024 threads then exceed the 64K-regs/CTA limit -> error 701 at launch.
__global__ __launch_bounds__(1024)
void scan_kernel() {
    __shared__ int part[1024];
    const int tid = threadIdx.x;
    const int CH = (NN + 1023) / 1024;   // 98
    const int base = tid * CH;
    int sum = 0;
    for (int i = 0; i < CH; i++) {
        int idx = base + i;
        if (idx < NN) sum += g_degi[idx];
    }
    part[tid] = sum;
    __syncthreads();
    // inclusive Hillis-Steele
    for (int off = 1; off < 1024; off <<= 1) {
        int v = (tid >= off) ? part[tid - off] : 0;
        __syncthreads();
        part[tid] += v;
        __syncthreads();
    }
    int run = (tid == 0) ? 0 : part[tid - 1];
    for (int i = 0; i < CH; i++) {
        int idx = base + i;
        if (idx < NN) { g_rowptr[idx] = run; run += g_degi[idx]; }
    }
    if (tid == 1023) g_rowptr[NN] = run;
}

// ---------------- scatter edges into CSR (by dst) ----------------
__global__ __launch_bounds__(256)
void scatter_kernel(const void* __restrict__ ei_raw) {
    int e = blockIdx.x * blockDim.x + threadIdx.x;
    if (e >= EE) return;
    int s, d; load_edge(ei_raw, e, s, d);
    int pos = g_rowptr[d] + atomicAdd(&g_cursor[d], 1);
    g_csr[pos] = s;
}

// ---------------- pull aggregation: out[n] = dinv[n]*sum_s dinv[s]*feat[s] + 2*dinv[n]^2*feat[n]
// one CTA of C threads per node; each thread owns one channel
template<int PHASE>
__global__ __launch_bounds__(256)
void gather_kernel(const float* __restrict__ xin) {
    constexpr int C = (PHASE == 0) ? DIN : HH;
    const float* feat = (PHASE == 0) ? xin : (const float*)g_h;
    float*       out  = (PHASE == 0) ? g_z1 : g_z2;

    const int n   = blockIdx.x;
    const int tid = threadIdx.x;

    __shared__ int   s_src[64];
    __shared__ float s_w[64];

    const int beg = g_rowptr[n];
    const int end = g_rowptr[n + 1];
    const float dn = g_dinv[n];

    float acc = 0.0f;
    for (int base = beg; base < end; base += 64) {
        int cnt = min(64, end - base);
        __syncthreads();
        if (tid < cnt) {
            int s = g_csr[base + tid];
            s_src[tid] = s;
            s_w[tid]   = g_dinv[s];
        }
        __syncthreads();
        int i = 0;
        for (; i + 4 <= cnt; i += 4) {
            float a0 = feat[(size_t)s_src[i + 0] * C + tid];
            float a1 = feat[(size_t)s_src[i + 1] * C + tid];
            float a2 = feat[(size_t)s_src[i + 2] * C + tid];
            float a3 = feat[(size_t)s_src[i + 3] * C + tid];
            acc = fmaf(s_w[i + 0], a0, acc);
            acc = fmaf(s_w[i + 1], a1, acc);
            acc = fmaf(s_w[i + 2], a2, acc);
            acc = fmaf(s_w[i + 3], a3, acc);
        }
        for (; i < cnt; i++)
            acc = fmaf(s_w[i], feat[(size_t)s_src[i] * C + tid], acc);
    }
    float self = feat[(size_t)n * C + tid];
    out[(size_t)n * C + tid] = dn * acc + 2.0f * dn * dn * self;
}

// ---------------- fused SGEMM 128x128, 256 threads, TM=TN=8 ----------------
// MODE 0: relu epilogue        (GEMM1)  ASRC=1 (g_z1)  DST=1 (g_h)
// MODE 1: softplus epilogue    (GEMM2)  ASRC=2 (g_z2)  DST=0 (param)
// MODE 2: A' = tanh(sp(thr)*A) (GEMM3)  ASRC=0 (param) DST=0 (param)
#define BM 128
#define BN 128
#define BK 16

template<int MODE, int ASRC, int DSTSEL>
__global__ __launch_bounds__(256, 2)
void sgemm_kernel(const float* __restrict__ Aparam, const float* __restrict__ B,
                  const float* __restrict__ bias, float* __restrict__ Cparam,
                  int Mrows, int K, int Ncols, const float* __restrict__ thr) {
    const float* A = (ASRC == 1) ? (const float*)g_z1
                   : (ASRC == 2) ? (const float*)g_z2
                                 : Aparam;
    float* Cp = (DSTSEL == 1) ? (float*)g_h : Cparam;

    __shared__ float As[BK][BM + 4];
    __shared__ float Bs[BK][BN + 4];

    float sp_t = 1.0f;
    if (MODE == 2) {
        float t = *thr;
        sp_t = fmaxf(t, 0.0f) + log1pf(expf(-fabsf(t)));
    }

    const int tid = threadIdx.x;
    const int tx = tid & 15;       // 0..15 -> col group of 8
    const int ty = tid >> 4;       // 0..15 -> row group of 8
    const int rowBase = blockIdx.y * BM;
    const int colBase = blockIdx.x * BN;

    // A-load mapping: row ar = tid>>1, k-chunk = (tid&1)*8 (two float4s)
    const int ar  = tid >> 1;
    const int akc = (tid & 1) * 8;
    // B-load mapping: row bk = tid>>4, col chunk = (tid&15)*8 (two float4s)
    const int bk  = tid >> 4;
    const int bc  = (tid & 15) * 8;

    float acc[8][8];
#pragma unroll
    for (int i = 0; i < 8; i++)
#pragma unroll
        for (int j = 0; j < 8; j++) acc[i][j] = 0.0f;

    for (int k0 = 0; k0 < K; k0 += BK) {
        // ---- load A tile (BM x BK), stored transposed As[kk][r]
        {
            int gr = rowBase + ar;
#pragma unroll
            for (int c = 0; c < 2; c++) {
                int gk = k0 + akc + c * 4;
                float4 v = make_float4(0.f, 0.f, 0.f, 0.f);
                if (gr < Mrows && gk < K)   // K,gk multiples of 4 -> full vec valid
                    v = *reinterpret_cast<const float4*>(&A[(size_t)gr * K + gk]);
                if (MODE == 2) {
                    v.x = tanhf(sp_t * v.x); v.y = tanhf(sp_t * v.y);
                    v.z = tanhf(sp_t * v.z); v.w = tanhf(sp_t * v.w);
                }
                int kk = akc + c * 4;
                As[kk + 0][ar] = v.x;
                As[kk + 1][ar] = v.y;
                As[kk + 2][ar] = v.z;
                As[kk + 3][ar] = v.w;
            }
        }
        // ---- load B tile (BK x BN)
        {
            int gk = k0 + bk;
#pragma unroll
            for (int c = 0; c < 2; c++) {
                int gc = colBase + bc + c * 4;
                float4 v = make_float4(0.f, 0.f, 0.f, 0.f);
                if (gk < K && gc < Ncols)   // Ncols,gc multiples of 4 -> full vec valid
                    v = *reinterpret_cast<const float4*>(&B[(size_t)gk * Ncols + gc]);
                *reinterpret_cast<float4*>(&Bs[bk][bc + c * 4]) = v;
            }
        }
        __syncthreads();
#pragma unroll
        for (int kk = 0; kk < BK; kk++) {
            float4 a0 = *reinterpret_cast<const float4*>(&As[kk][ty * 8]);
            float4 a1 = *reinterpret_cast<const float4*>(&As[kk][ty * 8 + 4]);
            float4 b0 = *reinterpret_cast<const float4*>(&Bs[kk][tx * 8]);
            float4 b1 = *reinterpret_cast<const float4*>(&Bs[kk][tx * 8 + 4]);
            float av[8] = {a0.x, a0.y, a0.z, a0.w, a1.x, a1.y, a1.z, a1.w};
            float bv[8] = {b0.x, b0.y, b0.z, b0.w, b1.x, b1.y, b1.z, b1.w};
#pragma unroll
            for (int i = 0; i < 8; i++)
#pragma unroll
                for (int j = 0; j < 8; j++)
                    acc[i][j] = fmaf(av[i], bv[j], acc[i][j]);
        }
        __syncthreads();
    }

#pragma unroll
    for (int i = 0; i < 8; i++) {
        int gr = rowBase + ty * 8 + i;
        if (gr >= Mrows) continue;
#pragma unroll
        for (int j = 0; j < 8; j++) {
            int gc = colBase + tx * 8 + j;
            if (gc >= Ncols) continue;
            float v = acc[i][j] + bias[gc];
            if (MODE == 0) v = fmaxf(v, 0.0f);
            else if (MODE == 1) v = fmaxf(v, 0.0f) + log1pf(expf(-fabsf(v)));
            Cp[(size_t)gr * Ncols + gc] = v;
        }
    }
}

// ---------------- launch: ONLY kernel launches ----------------
extern "C" void kernel_launch(void* const* d_in, const int* in_sizes, int n_in,
                              void* d_out, int out_size) {
    const float* x    = (const float*)d_in[0];
    const void*  ei   = d_in[1];                 // int32 or int64 — detected on device
    const float* W1   = (const float*)d_in[2];
    const float* b1   = (const float*)d_in[3];
    const float* W2   = (const float*)d_in[4];
    const float* b2   = (const float*)d_in[5];
    const float* Wout = (const float*)d_in[6];
    const float* bout = (const float*)d_in[7];
    const float* thr  = (const float*)d_in[8];

    float* mr = (float*)d_out;                       // [N, M]
    float* y  = (float*)d_out + (size_t)NN * MM;     // [N, O]

    const int T = 256;

    // CSR build
    detect_dtype_kernel<<<1, 32>>>(ei);
    zero_counts_kernel<<<(NN + T - 1) / T, T>>>();
    count_deg_kernel<<<(EE + T - 1) / T, T>>>(ei);
    scan_kernel<<<1, 1024>>>();
    finalize_dinv_kernel<<<(NN + T - 1) / T, T>>>();
    scatter_kernel<<<(EE + T - 1) / T, T>>>(ei);

    // z1 = S x + self*x   (pull, no atomics)
    gather_kernel<0><<<NN, DIN>>>(x);

    // h = relu(z1 @ W1 + b1)
    {
        dim3 grid((HH + BN - 1) / BN, (NN + BM - 1) / BM);
        sgemm_kernel<0, 1, 1><<<grid, 256>>>(nullptr, W1, b1, nullptr, NN, DIN, HH, nullptr);
    }

    // z2 = S h + self*h
    gather_kernel<1><<<NN, HH>>>(nullptr);

    // mr = softplus(z2 @ W2 + b2)
    {
        dim3 grid((MM + BN - 1) / BN, (NN + BM - 1) / BM);
        sgemm_kernel<1, 2, 0><<<grid, 256>>>(nullptr, W2, b2, mr, NN, HH, MM, nullptr);
    }

    // y = tanh(softplus(thr) * mr) @ Wout + bout
    {
        dim3 grid((OO + BN - 1) / BN, (NN + BM - 1) / BM);
        sgemm_kernel<2, 0, 0><<<grid, 256>>>(mr, Wout, bout, y, NN, MM, OO, thr);
    }
}

// round 16
// speedup vs baseline: 3.5654x; 1.6051x over previous
#include <cuda_runtime.h>
#include <math.h>

#define NN 100000
#define EE 3200000
#define DIN 128
#define HH 256
#define MM 500
#define OO 100

// ---------------- scratch: __device__ globals (sanctioned; no dynamic alloc) ----
__device__ __align__(16) float g_dinv[NN];            // deg^-1/2
__device__ __align__(16) int   g_degi[NN];            // int degree
__device__ __align__(16) int   g_cursor[NN];          // scatter cursors
__device__ __align__(16) int   g_rowptr[NN + 1];      // CSR row pointers (by dst)
__device__ __align__(16) int   g_csr[EE];             // CSR src indices
__device__ __align__(16) float g_z1[(size_t)NN*DIN];  // Sx + self*x
__device__ __align__(16) float g_h [(size_t)NN*HH];   // relu(z1 @ W1 + b1)
__device__ __align__(16) float g_z2[(size_t)NN*HH];   // Sh + self*h
__device__ int g_is64;                                // edge dtype flag

// ---------------- edge dtype detection ----------------
__global__ __launch_bounds__(32)
void detect_dtype_kernel(const void* __restrict__ ei_raw) {
    if (threadIdx.x == 0 && blockIdx.x == 0) {
        const long long* e64 = (const long long*)ei_raw;
        int ok = 1;
        for (int k = 0; k < 16; k++) {
            long long v = e64[k];
            if (v < 0 || v >= NN) ok = 0;
        }
        g_is64 = ok;
    }
}

__device__ __forceinline__ void load_edge(const void* ei_raw, int e, int& s, int& d) {
    if (g_is64) {
        const long long* e64 = (const long long*)ei_raw;
        s = (int)e64[e];
        d = (int)e64[(size_t)EE + e];
    } else {
        const int* e32 = (const int*)ei_raw;
        s = e32[e];
        d = e32[EE + e];
    }
}

// ---------------- degree count ----------------
__global__ __launch_bounds__(256)
void zero_counts_kernel() {
    int i = blockIdx.x * blockDim.x + threadIdx.x;
    if (i < NN) { g_degi[i] = 0; g_cursor[i] = 0; }
}

__global__ __launch_bounds__(256)
void count_deg_kernel(const void* __restrict__ ei_raw) {
    int e = blockIdx.x * blockDim.x + threadIdx.x;
    if (e >= EE) return;
    int s, d; load_edge(ei_raw, e, s, d);
    atomicAdd(&g_degi[d], 1);
}

__global__ __launch_bounds__(256)
void finalize_dinv_kernel() {
    int i = blockIdx.x * blockDim.x + threadIdx.x;
    if (i < NN) g_dinv[i] = rsqrtf((float)g_degi[i] + 2.0f);
}

// ---------------- exclusive scan of degrees -> rowptr (single block, vectorized) ----
__global__ __launch_bounds__(1024)
void scan_kernel() {
    __shared__ int part[1024];
    const int tid = threadIdx.x;
    const int CH = 100;                 // 1024*100 = 102400 >= NN; base 16B-aligned
    const int base = tid * CH;
    int sum = 0;
    if (base + CH <= NN) {
        const int4* p = reinterpret_cast<const int4*>(g_degi + base);
#pragma unroll
        for (int i = 0; i < CH / 4; i++) {
            int4 v = p[i];
            sum += v.x + v.y + v.z + v.w;
        }
    } else {
        for (int i = 0; i < CH; i++) {
            int idx = base + i;
            if (idx < NN) sum += g_degi[idx];
        }
    }
    part[tid] = sum;
    __syncthreads();
    for (int off = 1; off < 1024; off <<= 1) {
        int v = (tid >= off) ? part[tid - off] : 0;
        __syncthreads();
        part[tid] += v;
        __syncthreads();
    }
    int run = (tid == 0) ? 0 : part[tid - 1];
    if (base + CH <= NN) {
        const int4* p = reinterpret_cast<const int4*>(g_degi + base);
        int4* q = reinterpret_cast<int4*>(g_rowptr + base);
#pragma unroll
        for (int i = 0; i < CH / 4; i++) {
            int4 v = p[i];
            int4 w;
            w.x = run; run += v.x;
            w.y = run; run += v.y;
            w.z = run; run += v.z;
            w.w = run; run += v.w;
            q[i] = w;
        }
    } else {
        for (int i = 0; i < CH; i++) {
            int idx = base + i;
            if (idx < NN) { g_rowptr[idx] = run; run += g_degi[idx]; }
        }
    }
    if (tid == 1023) g_rowptr[NN] = run;
}

// ---------------- scatter edges into CSR (by dst) ----------------
__global__ __launch_bounds__(256)
void scatter_kernel(const void* __restrict__ ei_raw) {
    int e = blockIdx.x * blockDim.x + threadIdx.x;
    if (e >= EE) return;
    int s, d; load_edge(ei_raw, e, s, d);
    int pos = g_rowptr[d] + atomicAdd(&g_cursor[d], 1);
    g_csr[pos] = s;
}

// ---------------- pull aggregation ----------------
template<int PHASE>
__global__ __launch_bounds__(256)
void gather_kernel(const float* __restrict__ xin) {
    constexpr int C = (PHASE == 0) ? DIN : HH;
    const float* feat = (PHASE == 0) ? xin : (const float*)g_h;
    float*       out  = (PHASE == 0) ? g_z1 : g_z2;

    const int n   = blockIdx.x;
    const int tid = threadIdx.x;

    __shared__ int   s_src[64];
    __shared__ float s_w[64];

    const int beg = g_rowptr[n];
    const int end = g_rowptr[n + 1];
    const float dn = g_dinv[n];

    float acc = 0.0f;
    for (int base = beg; base < end; base += 64) {
        int cnt = min(64, end - base);
        __syncthreads();
        if (tid < cnt) {
            int s = g_csr[base + tid];
            s_src[tid] = s;
            s_w[tid]   = g_dinv[s];
        }
        __syncthreads();
        int i = 0;
        for (; i + 4 <= cnt; i += 4) {
            float a0 = feat[(size_t)s_src[i + 0] * C + tid];
            float a1 = feat[(size_t)s_src[i + 1] * C + tid];
            float a2 = feat[(size_t)s_src[i + 2] * C + tid];
            float a3 = feat[(size_t)s_src[i + 3] * C + tid];
            acc = fmaf(s_w[i + 0], a0, acc);
            acc = fmaf(s_w[i + 1], a1, acc);
            acc = fmaf(s_w[i + 2], a2, acc);
            acc = fmaf(s_w[i + 3], a3, acc);
        }
        for (; i < cnt; i++)
            acc = fmaf(s_w[i], feat[(size_t)s_src[i] * C + tid], acc);
    }
    float self = feat[(size_t)n * C + tid];
    out[(size_t)n * C + tid] = dn * acc + 2.0f * dn * dn * self;
}

// ---------------- tf32 tensor-core GEMM: C = epi(A' @ B + bias) ----------------
// m16n8k8 mma.sync; 128x128 CTA tile; 8 warps as 2(row)x4(col), warp tile 64x32.
// MODE 0: relu epilogue        (GEMM1)  ASRC=1 (g_z1)  DST=1 (g_h)
// MODE 1: softplus epilogue    (GEMM2)  ASRC=2 (g_z2)  DST=0 (param)
// MODE 2: A' = tanh(sp(thr)*A) (GEMM3)  ASRC=0 (param) DST=0 (param)
#define BM 128
#define BN 128
#define BK 16
#define AS_STRIDE 133
#define BS_STRIDE 132

__device__ __forceinline__ unsigned f2tf32(float f) {
    unsigned u;
    asm("cvt.rna.tf32.f32 %0, %1;" : "=r"(u) : "f"(f));
    return u;
}

__device__ __forceinline__ void mma_tf32(float* c, unsigned a0, unsigned a1,
                                         unsigned a2, unsigned a3,
                                         unsigned b0, unsigned b1) {
    asm("mma.sync.aligned.m16n8k8.row.col.f32.tf32.tf32.f32 "
        "{%0,%1,%2,%3},{%4,%5,%6,%7},{%8,%9},{%0,%1,%2,%3};"
        : "+f"(c[0]), "+f"(c[1]), "+f"(c[2]), "+f"(c[3])
        : "r"(a0), "r"(a1), "r"(a2), "r"(a3), "r"(b0), "r"(b1));
}

template<int MODE, int ASRC, int DSTSEL>
__global__ __launch_bounds__(256, 2)
void mma_gemm_kernel(const float* __restrict__ Aparam, const float* __restrict__ B,
                     const float* __restrict__ bias, float* __restrict__ Cparam,
                     int Mrows, int K, int Ncols, const float* __restrict__ thr) {
    const float* A = (ASRC == 1) ? (const float*)g_z1
                   : (ASRC == 2) ? (const float*)g_z2
                                 : Aparam;
    float* Cp = (DSTSEL == 1) ? (float*)g_h : Cparam;

    __shared__ unsigned As[BK * AS_STRIDE];   // [k][m], padded
    __shared__ unsigned Bs[BK * BS_STRIDE];   // [k][n], padded

    float sp_t = 1.0f;
    if (MODE == 2) {
        float t = *thr;
        sp_t = fmaxf(t, 0.0f) + log1pf(expf(-fabsf(t)));
    }

    const int tid  = threadIdx.x;
    const int wid  = tid >> 5;
    const int lane = tid & 31;
    const int g    = lane >> 2;       // group id 0..7
    const int tg   = lane & 3;        // thread-in-group 0..3

    const int warpRow = wid >> 2;     // 0..1 -> 64 rows
    const int warpCol = wid & 3;      // 0..3 -> 32 cols
    const int rowBase = blockIdx.y * BM;
    const int colBase = blockIdx.x * BN;
    const int wm = warpRow * 64;
    const int wn = warpCol * 32;

    // global->smem load mappings
    const int ar  = tid >> 1;             // A row 0..127
    const int akc = (tid & 1) * 8;        // A k chunk {0,8}
    const int bk  = tid >> 4;             // B k row 0..15
    const int bc  = (tid & 15) * 8;       // B col chunk

    float acc[4][4][4];
#pragma unroll
    for (int i = 0; i < 4; i++)
#pragma unroll
        for (int j = 0; j < 4; j++)
#pragma unroll
            for (int q = 0; q < 4; q++) acc[i][j][q] = 0.0f;

    for (int k0 = 0; k0 < K; k0 += BK) {
        // ---- A tile (BM x BK) -> As[k][m] (tf32)
        {
            int gr = rowBase + ar;
#pragma unroll
            for (int c = 0; c < 2; c++) {
                int gk = k0 + akc + c * 4;
                float4 v = make_float4(0.f, 0.f, 0.f, 0.f);
                if (gr < Mrows && gk + 4 <= K)
                    v = *reinterpret_cast<const float4*>(&A[(size_t)gr * K + gk]);
                if (MODE == 2) {
                    v.x = tanhf(sp_t * v.x); v.y = tanhf(sp_t * v.y);
                    v.z = tanhf(sp_t * v.z); v.w = tanhf(sp_t * v.w);
                }
                int kk = akc + c * 4;
                As[(kk + 0) * AS_STRIDE + ar] = f2tf32(v.x);
                As[(kk + 1) * AS_STRIDE + ar] = f2tf32(v.y);
                As[(kk + 2) * AS_STRIDE + ar] = f2tf32(v.z);
                As[(kk + 3) * AS_STRIDE + ar] = f2tf32(v.w);
            }
        }
        // ---- B tile (BK x BN) -> Bs[k][n] (tf32)
        {
            int gk = k0 + bk;
#pragma unroll
            for (int c = 0; c < 2; c++) {
                int gc = colBase + bc + c * 4;
                float4 v = make_float4(0.f, 0.f, 0.f, 0.f);
                if (gk < K && gc + 4 <= Ncols)
                    v = *reinterpret_cast<const float4*>(&B[(size_t)gk * Ncols + gc]);
                uint4 u;
                u.x = f2tf32(v.x); u.y = f2tf32(v.y);
                u.z = f2tf32(v.z); u.w = f2tf32(v.w);
                *reinterpret_cast<uint4*>(&Bs[bk * BS_STRIDE + bc + c * 4]) = u;
            }
        }
        __syncthreads();

#pragma unroll
        for (int ks = 0; ks < BK; ks += 8) {
            // B fragments: 4 n8-tiles
            unsigned bf[4][2];
#pragma unroll
            for (int j = 0; j < 4; j++) {
                int nb = wn + j * 8 + g;
                bf[j][0] = Bs[(ks + tg) * BS_STRIDE + nb];
                bf[j][1] = Bs[(ks + tg + 4) * BS_STRIDE + nb];
            }
#pragma unroll
            for (int i = 0; i < 4; i++) {
                int mb = wm + i * 16;
                unsigned a0 = As[(ks + tg) * AS_STRIDE + mb + g];
                unsigned a1 = As[(ks + tg) * AS_STRIDE + mb + g + 8];
                unsigned a2 = As[(ks + tg + 4) * AS_STRIDE + mb + g];
                unsigned a3 = As[(ks + tg + 4) * AS_STRIDE + mb + g + 8];
#pragma unroll
                for (int j = 0; j < 4; j++)
                    mma_tf32(acc[i][j], a0, a1, a2, a3, bf[j][0], bf[j][1]);
            }
        }
        __syncthreads();
    }

    // ---- epilogue
#pragma unroll
    for (int i = 0; i < 4; i++) {
        int r0 = rowBase + wm + i * 16 + g;
        int r1 = r0 + 8;
#pragma unroll
        for (int j = 0; j < 4; j++) {
            int cb = colBase + wn + j * 8 + 2 * tg;
            if (cb + 2 > Ncols) continue;
            float bz0 = bias[cb], bz1 = bias[cb + 1];
            float v0 = acc[i][j][0] + bz0;
            float v1 = acc[i][j][1] + bz1;
            float v2 = acc[i][j][2] + bz0;
            float v3 = acc[i][j][3] + bz1;
            if (MODE == 0) {
                v0 = fmaxf(v0, 0.f); v1 = fmaxf(v1, 0.f);
                v2 = fmaxf(v2, 0.f); v3 = fmaxf(v3, 0.f);
            } else if (MODE == 1) {
                v0 = fmaxf(v0, 0.f) + log1pf(expf(-fabsf(v0)));
                v1 = fmaxf(v1, 0.f) + log1pf(expf(-fabsf(v1)));
                v2 = fmaxf(v2, 0.f) + log1pf(expf(-fabsf(v2)));
                v3 = fmaxf(v3, 0.f) + log1pf(expf(-fabsf(v3)));
            }
            if (r0 < Mrows)
                *reinterpret_cast<float2*>(&Cp[(size_t)r0 * Ncols + cb]) = make_float2(v0, v1);
            if (r1 < Mrows)
                *reinterpret_cast<float2*>(&Cp[(size_t)r1 * Ncols + cb]) = make_float2(v2, v3);
        }
    }
}

// ---------------- launch: ONLY kernel launches ----------------
extern "C" void kernel_launch(void* const* d_in, const int* in_sizes, int n_in,
                              void* d_out, int out_size) {
    const float* x    = (const float*)d_in[0];
    const void*  ei   = d_in[1];
    const float* W1   = (const float*)d_in[2];
    const float* b1   = (const float*)d_in[3];
    const float* W2   = (const float*)d_in[4];
    const float* b2   = (const float*)d_in[5];
    const float* Wout = (const float*)d_in[6];
    const float* bout = (const float*)d_in[7];
    const float* thr  = (const float*)d_in[8];

    float* mr = (float*)d_out;                       // [N, M]
    float* y  = (float*)d_out + (size_t)NN * MM;     // [N, O]

    const int T = 256;

    // CSR build
    detect_dtype_kernel<<<1, 32>>>(ei);
    zero_counts_kernel<<<(NN + T - 1) / T, T>>>();
    count_deg_kernel<<<(EE + T - 1) / T, T>>>(ei);
    scan_kernel<<<1, 1024>>>();
    finalize_dinv_kernel<<<(NN + T - 1) / T, T>>>();
    scatter_kernel<<<(EE + T - 1) / T, T>>>(ei);

    // z1 = S x + self*x
    gather_kernel<0><<<NN, DIN>>>(x);

    // h = relu(z1 @ W1 + b1)
    {
        dim3 grid((HH + BN - 1) / BN, (NN + BM - 1) / BM);
        mma_gemm_kernel<0, 1, 1><<<grid, 256>>>(nullptr, W1, b1, nullptr, NN, DIN, HH, nullptr);
    }

    // z2 = S h + self*h
    gather_kernel<1><<<NN, HH>>>(nullptr);

    // mr = softplus(z2 @ W2 + b2)
    {
        dim3 grid((MM + BN - 1) / BN, (NN + BM - 1) / BM);
        mma_gemm_kernel<1, 2, 0><<<grid, 256>>>(nullptr, W2, b2, mr, NN, HH, MM, nullptr);
    }

    // y = tanh(softplus(thr) * mr) @ Wout + bout
    {
        dim3 grid((OO + BN - 1) / BN, (NN + BM - 1) / BM);
        mma_gemm_kernel<2, 0, 0><<<grid, 256>>>(mr, Wout, bout, y, NN, MM, OO, thr);
    }
}